// round 1
// baseline (speedup 1.0000x reference)
#include <cuda_runtime.h>
#include <math.h>

// Problem constants
#define D_DIM   512
#define H_DIM   256
#define R_DIM   95
#define KJ      64     // K*8 flattened multivector width
#define TB      64     // batch rows per block
#define KC      32     // k-chunk for smem staging
#define NTHREADS 256

// smem strides (floats), padded against bank conflicts
#define ASTRIDE (TB + 1)   // 65
#define XSTRIDE 260
#define MSTRIDE 65
#define TSTRIDE 97

// smem layout (floats)
#define OFF_AS   0
#define OFF_BS   (OFF_AS + KC * ASTRIDE)          // 2080
#define OFF_X    (OFF_BS + KC * H_DIM)            // 2080 + 8192 = 10272
#define OFF_M    (OFF_X + TB * XSTRIDE)           // +16640 = 26912
#define OFF_T    (OFF_M + 2 * TB * MSTRIDE)       // +8320  = 35232
#define SMEM_FLOATS (OFF_T + KJ * TSTRIDE)        // +6208  = 41440
#define SMEM_BYTES  (SMEM_FLOATS * 4)             // 165760

__global__ __launch_bounds__(NTHREADS, 1)
void clifford_fused_kernel(
    const float* __restrict__ h_perp, const float* __restrict__ h_vuln,
    const float* __restrict__ Wp1, const float* __restrict__ bp1,
    const float* __restrict__ lgp, const float* __restrict__ lbp,
    const float* __restrict__ Wp2, const float* __restrict__ bp2,
    const float* __restrict__ Wv1, const float* __restrict__ bv1,
    const float* __restrict__ lgv, const float* __restrict__ lbv,
    const float* __restrict__ Wv2, const float* __restrict__ bv2,
    const float* __restrict__ Tm, const float* __restrict__ gw,
    float* __restrict__ out)
{
    extern __shared__ float smem[];
    float* As   = smem + OFF_AS;   // [KC][ASTRIDE] transposed A chunk
    float* Bs   = smem + OFF_BS;   // [KC][H_DIM]   W1 chunk (reused for W2 chunk [KC][64])
    float* xbuf = smem + OFF_X;    // [TB][XSTRIDE] hidden activations (reused as P with MSTRIDE)
    float* mbuf = smem + OFF_M;    // [2][TB][MSTRIDE] multivectors mp, mv
    float* Tbuf = smem + OFF_T;    // [KJ][TSTRIDE] T transposed, pre-scaled by 1/8
    float* pbuf = xbuf;            // P[TB][MSTRIDE], reuses xbuf storage

    const int tid  = threadIdx.x;
    const int ty   = tid >> 4;     // 0..15
    const int tx   = tid & 15;     // 0..15
    const int lane = tid & 31;
    const int wid  = tid >> 5;     // 0..7
    const int r0   = blockIdx.x * TB;

    // ---- Stage T (R,K,8) -> Tbuf[kj][r], scaled by 1/K ----
    for (int idx = tid; idx < R_DIM * KJ; idx += NTHREADS) {
        int r  = idx >> 6;
        int kj = idx & 63;
        Tbuf[kj * TSTRIDE + r] = Tm[idx] * 0.125f;
    }

    // grade weights -> regs
    float gwr[8];
#pragma unroll
    for (int n = 0; n < 8; ++n) gwr[n] = gw[n];

    // basis order: positions -> masks (and mask -> position is the same table)
    const int MASKc[8] = {0, 1, 2, 4, 3, 5, 6, 7};

    // ================= two projections =================
    for (int p = 0; p < 2; ++p) {
        const float* hptr = p ? h_vuln : h_perp;
        const float* W1   = p ? Wv1 : Wp1;
        const float* b1   = p ? bv1 : bp1;
        const float* lg   = p ? lgv : lgp;
        const float* lb   = p ? lbv : lbp;
        const float* W2   = p ? Wv2 : Wp2;
        const float* b2   = p ? bv2 : bp2;
        float* mb = mbuf + p * TB * MSTRIDE;

        // ---- GEMM1: x[64][256] = h_tile[64][512] @ W1[512][256] ----
        float acc[4][16];
#pragma unroll
        for (int i = 0; i < 4; ++i)
#pragma unroll
            for (int j = 0; j < 16; ++j) acc[i][j] = 0.f;

        for (int kk = 0; kk < D_DIM; kk += KC) {
            __syncthreads();   // protect previous chunk's reads
            // A chunk 64x32, stored transposed As[c][r]
#pragma unroll
            for (int e = 0; e < 8; ++e) {
                int idx = e * NTHREADS + tid;
                int rr = idx >> 5;
                int cc = idx & 31;
                As[cc * ASTRIDE + rr] = hptr[(r0 + rr) * D_DIM + kk + cc];
            }
            // B chunk 32x256
#pragma unroll 8
            for (int e = 0; e < 32; ++e) {
                int idx = e * NTHREADS + tid;
                int kr = idx >> 8;
                int cc = idx & 255;
                Bs[kr * H_DIM + cc] = W1[(kk + kr) * H_DIM + cc];
            }
            __syncthreads();
#pragma unroll
            for (int k = 0; k < KC; ++k) {
                float a[4], b[16];
#pragma unroll
                for (int i = 0; i < 4; ++i) a[i] = As[k * ASTRIDE + ty * 4 + i];
#pragma unroll
                for (int j = 0; j < 16; ++j) b[j] = Bs[k * H_DIM + tx + 16 * j];
#pragma unroll
                for (int i = 0; i < 4; ++i)
#pragma unroll
                    for (int j = 0; j < 16; ++j) acc[i][j] += a[i] * b[j];
            }
        }
        __syncthreads();

        // bias + write x to smem
#pragma unroll
        for (int i = 0; i < 4; ++i)
#pragma unroll
            for (int j = 0; j < 16; ++j) {
                int col = tx + 16 * j;
                xbuf[(ty * 4 + i) * XSTRIDE + col] = acc[i][j] + b1[col];
            }
        __syncthreads();

        // ---- LayerNorm + exact GELU, one row per warp-iteration ----
        for (int rr = 0; rr < 8; ++rr) {
            int row = wid * 8 + rr;
            float v[8];
            float s = 0.f, s2 = 0.f;
#pragma unroll
            for (int q = 0; q < 8; ++q) {
                v[q] = xbuf[row * XSTRIDE + lane + 32 * q];
                s  += v[q];
                s2 += v[q] * v[q];
            }
#pragma unroll
            for (int o = 16; o > 0; o >>= 1) {
                s  += __shfl_xor_sync(0xFFFFFFFFu, s,  o);
                s2 += __shfl_xor_sync(0xFFFFFFFFu, s2, o);
            }
            float mu  = s * (1.f / 256.f);
            float var = s2 * (1.f / 256.f) - mu * mu;
            float rs  = rsqrtf(var + 1e-5f);
#pragma unroll
            for (int q = 0; q < 8; ++q) {
                int col = lane + 32 * q;
                float y = (v[q] - mu) * rs * lg[col] + lb[col];
                float g = 0.5f * y * (1.f + erff(y * 0.70710678118654752f));
                xbuf[row * XSTRIDE + col] = g;
            }
        }
        __syncthreads();

        // ---- GEMM2: m[64][64] = x[64][256] @ W2[256][64] ----
        float acc2[4][4];
#pragma unroll
        for (int i = 0; i < 4; ++i)
#pragma unroll
            for (int j = 0; j < 4; ++j) acc2[i][j] = 0.f;

        for (int kk = 0; kk < H_DIM; kk += KC) {
            __syncthreads();   // protect Bs reuse
#pragma unroll
            for (int e = 0; e < 8; ++e) {
                int idx = e * NTHREADS + tid;
                int kr = idx >> 6;
                int cc = idx & 63;
                Bs[kr * KJ + cc] = W2[(kk + kr) * KJ + cc];
            }
            __syncthreads();
#pragma unroll
            for (int k = 0; k < KC; ++k) {
                float a[4], b[4];
#pragma unroll
                for (int i = 0; i < 4; ++i) a[i] = xbuf[(ty * 4 + i) * XSTRIDE + kk + k];
#pragma unroll
                for (int j = 0; j < 4; ++j) b[j] = Bs[k * KJ + tx + 16 * j];
#pragma unroll
                for (int i = 0; i < 4; ++i)
#pragma unroll
                    for (int j = 0; j < 4; ++j) acc2[i][j] += a[i] * b[j];
            }
        }
        __syncthreads();
#pragma unroll
        for (int i = 0; i < 4; ++i)
#pragma unroll
            for (int j = 0; j < 4; ++j) {
                int col = tx + 16 * j;
                mb[(ty * 4 + i) * MSTRIDE + col] = acc2[i][j] + b2[col];
            }
    }
    __syncthreads();

    // ---- Cayley contraction to P (gw-general) ----
    // Q[m] = sum_j sign(m,j) gw[idx(m^j)] mv[j];  P[j] = sum_i sign(i,j) mp[i] Q[idx(i^j)]
    {
        int row   = tid & 63;
        int kbase = (tid >> 6) * 2;
        const float* mp = mbuf + row * MSTRIDE;
        const float* mv = mbuf + TB * MSTRIDE + row * MSTRIDE;
#pragma unroll
        for (int kk2 = 0; kk2 < 2; ++kk2) {
            int k = kbase + kk2;
            float mpv[8], mvv[8];
#pragma unroll
            for (int i = 0; i < 8; ++i) { mpv[i] = mp[k * 8 + i]; mvv[i] = mv[k * 8 + i]; }
            float Q[8];
#pragma unroll
            for (int m = 0; m < 8; ++m) {
                float q = 0.f;
#pragma unroll
                for (int j = 0; j < 8; ++j) {
                    int am = MASKc[m], bm = MASKc[j];
                    int sw = __popc((am >> 1) & bm) + __popc((am >> 2) & bm);
                    float sg = (sw & 1) ? -1.f : 1.f;
                    q += sg * gwr[MASKc[am ^ bm]] * mvv[j];
                }
                Q[m] = q;
            }
#pragma unroll
            for (int j = 0; j < 8; ++j) {
                float pv = 0.f;
#pragma unroll
                for (int i = 0; i < 8; ++i) {
                    int am = MASKc[i], bm = MASKc[j];
                    int sw = __popc((am >> 1) & bm) + __popc((am >> 2) & bm);
                    float sg = (sw & 1) ? -1.f : 1.f;
                    pv += sg * mpv[i] * Q[MASKc[am ^ bm]];
                }
                pbuf[row * MSTRIDE + k * 8 + j] = pv;
            }
        }
    }
    __syncthreads();

    // ---- Final: out[64][95] = P[64][64] @ Tbuf[64][95] (Tbuf pre-scaled 1/8) ----
    {
        float acc3[4][6];
#pragma unroll
        for (int i = 0; i < 4; ++i)
#pragma unroll
            for (int j = 0; j < 6; ++j) acc3[i][j] = 0.f;
#pragma unroll 8
        for (int k = 0; k < KJ; ++k) {
            float a[4], b[6];
#pragma unroll
            for (int i = 0; i < 4; ++i) a[i] = pbuf[(ty * 4 + i) * MSTRIDE + k];
#pragma unroll
            for (int j = 0; j < 6; ++j) {
                int col = tx + 16 * j;
                b[j] = (col < R_DIM) ? Tbuf[k * TSTRIDE + col] : 0.f;
            }
#pragma unroll
            for (int i = 0; i < 4; ++i)
#pragma unroll
                for (int j = 0; j < 6; ++j) acc3[i][j] += a[i] * b[j];
        }
#pragma unroll
        for (int i = 0; i < 4; ++i)
#pragma unroll
            for (int j = 0; j < 6; ++j) {
                int col = tx + 16 * j;
                if (col < R_DIM)
                    out[(r0 + ty * 4 + i) * R_DIM + col] = acc3[i][j];
            }
    }
}

extern "C" void kernel_launch(void* const* d_in, const int* in_sizes, int n_in,
                              void* d_out, int out_size) {
    const float* h_perp = (const float*)d_in[0];
    const float* h_vuln = (const float*)d_in[1];
    const float* Wp1 = (const float*)d_in[2];
    const float* bp1 = (const float*)d_in[3];
    const float* lgp = (const float*)d_in[4];
    const float* lbp = (const float*)d_in[5];
    const float* Wp2 = (const float*)d_in[6];
    const float* bp2 = (const float*)d_in[7];
    const float* Wv1 = (const float*)d_in[8];
    const float* bv1 = (const float*)d_in[9];
    const float* lgv = (const float*)d_in[10];
    const float* lbv = (const float*)d_in[11];
    const float* Wv2 = (const float*)d_in[12];
    const float* bv2 = (const float*)d_in[13];
    const float* Tm  = (const float*)d_in[14];
    const float* gw  = (const float*)d_in[15];
    float* out = (float*)d_out;

    int B = in_sizes[0] / D_DIM;       // 16384
    int grid = B / TB;                 // 256

    cudaFuncSetAttribute(clifford_fused_kernel,
                         cudaFuncAttributeMaxDynamicSharedMemorySize, SMEM_BYTES);
    clifford_fused_kernel<<<grid, NTHREADS, SMEM_BYTES>>>(
        h_perp, h_vuln, Wp1, bp1, lgp, lbp, Wp2, bp2,
        Wv1, bv1, lgv, lbv, Wv2, bv2, Tm, gw, out);
}

// round 3
// speedup vs baseline: 2.5801x; 2.5801x over previous
#include <cuda_runtime.h>
#include <cuda_bf16.h>
#include <cstdint>
#include <math.h>

// ----------------------------------------------------------------------------
// B=16384, D=512, H=256, R=95, KJ=64. TB=128 rows/CTA, 512 threads (16 warps,
// 4x4 warp grid). mma.sync m16n8k16 bf16 (base sm_103 target - no tcgen05).
// hi/lo bf16 split, 3 products, fp32 accumulate.
// ----------------------------------------------------------------------------

#define TB 128
#define NT 512

// smem byte offsets
#define OFF_X    0            // x slabs: hi [4 wn][128][128B], lo at +65536 (131072 total)
#define XLO      65536
#define OFF_A1   0            // GEMM1 A staging hi [128][144] (+lo at +18432), overlaps X
#define A1LO     18432
#define OFF_B1   36864        // GEMM1 B staging hi [256][144] (+lo at +36864)
#define B1LO     36864
#define OFF_MB   131072       // mbuf [2][128][65] f32 = 66560
#define OFF_TB   197632       // Tbuf [64][97] f32 = 24832
#define OFF_ST   222464       // stats [128][8] f32 = 4096
#define SMEM_BYTES 226560

#define SW(x) ((x) ^ (((x) >> 3) & 0x70))

static __device__ __forceinline__ uint32_t smem_u32(const void* p) {
    uint32_t a;
    asm("{ .reg .u64 t; cvta.to.shared.u64 t, %1; cvt.u32.u64 %0, t; }" : "=r"(a) : "l"(p));
    return a;
}

static __device__ __forceinline__ void ldsm4(uint32_t* r, uint32_t addr) {
    asm volatile("ldmatrix.sync.aligned.m8n8.x4.shared.b16 {%0,%1,%2,%3}, [%4];"
                 : "=r"(r[0]), "=r"(r[1]), "=r"(r[2]), "=r"(r[3]) : "r"(addr));
}

static __device__ __forceinline__ void mma16816(float* c, const uint32_t* a,
                                                uint32_t b0, uint32_t b1) {
    asm volatile(
        "mma.sync.aligned.m16n8k16.row.col.f32.bf16.bf16.f32 "
        "{%0,%1,%2,%3}, {%4,%5,%6,%7}, {%8,%9}, {%0,%1,%2,%3};"
        : "+f"(c[0]), "+f"(c[1]), "+f"(c[2]), "+f"(c[3])
        : "r"(a[0]), "r"(a[1]), "r"(a[2]), "r"(a[3]), "r"(b0), "r"(b1));
}

// hi/lo bf16 split of a float pair, packed (elem0 in low half)
static __device__ __forceinline__ void split2(float a0, float a1, uint32_t& hi, uint32_t& lo) {
    __nv_bfloat16 h0 = __float2bfloat16_rn(a0), h1 = __float2bfloat16_rn(a1);
    float f0 = __bfloat162float(h0), f1 = __bfloat162float(h1);
    __nv_bfloat16 l0 = __float2bfloat16_rn(a0 - f0), l1 = __float2bfloat16_rn(a1 - f1);
    hi = ((uint32_t)__bfloat16_as_ushort(h1) << 16) | (uint32_t)__bfloat16_as_ushort(h0);
    lo = ((uint32_t)__bfloat16_as_ushort(l1) << 16) | (uint32_t)__bfloat16_as_ushort(l0);
}

// weight scratch: W1^T u32[n=256][kp=256], W2^T u32[n=64][kp=128]  (kp = k/2 pairs)
__device__ __align__(16) uint32_t g_w1t_hi[2][256 * 256];
__device__ __align__(16) uint32_t g_w1t_lo[2][256 * 256];
__device__ __align__(16) uint32_t g_w2t_hi[2][64 * 128];
__device__ __align__(16) uint32_t g_w2t_lo[2][64 * 128];

__global__ void prep_kernel(const float* __restrict__ Wp1, const float* __restrict__ Wv1,
                            const float* __restrict__ Wp2, const float* __restrict__ Wv2) {
    int idx = blockIdx.x * blockDim.x + threadIdx.x;
    if (idx < 65536) {
        int n = idx >> 8, kp = idx & 255;
#pragma unroll
        for (int p = 0; p < 2; ++p) {
            const float* W1 = p ? Wv1 : Wp1;
            float a0 = W1[(2 * kp) * 256 + n];
            float a1 = W1[(2 * kp + 1) * 256 + n];
            uint32_t hi, lo;
            split2(a0, a1, hi, lo);
            g_w1t_hi[p][n * 256 + kp] = hi;
            g_w1t_lo[p][n * 256 + kp] = lo;
        }
    } else if (idx < 65536 + 8192) {
        int j = idx - 65536;
        int n = j >> 7, kp = j & 127;
#pragma unroll
        for (int p = 0; p < 2; ++p) {
            const float* W2 = p ? Wv2 : Wp2;
            float a0 = W2[(2 * kp) * 64 + n];
            float a1 = W2[(2 * kp + 1) * 64 + n];
            uint32_t hi, lo;
            split2(a0, a1, hi, lo);
            g_w2t_hi[p][n * 128 + kp] = hi;
            g_w2t_lo[p][n * 128 + kp] = lo;
        }
    }
}

__global__ __launch_bounds__(NT, 1)
void clifford_mma_kernel(
    const float* __restrict__ h_perp, const float* __restrict__ h_vuln,
    const float* __restrict__ bp1, const float* __restrict__ lgp,
    const float* __restrict__ lbp, const float* __restrict__ bp2,
    const float* __restrict__ bv1, const float* __restrict__ lgv,
    const float* __restrict__ lbv, const float* __restrict__ bv2,
    const float* __restrict__ Tm, const float* __restrict__ gw,
    float* __restrict__ out)
{
    extern __shared__ char smem[];
    const uint32_t sb = smem_u32(smem);
    const int tid = threadIdx.x;
    const int lane = tid & 31;
    const int wid = tid >> 5;
    const int wm = wid & 3;       // m-block: rows wm*32..+32
    const int wn = wid >> 2;      // n-block: cols wn*64..+64
    const int g = lane >> 2, t = lane & 3;
    const int g8 = lane & 7, m4 = lane >> 3;
    const int r0 = blockIdx.x * TB;

    float* mbuf  = (float*)(smem + OFF_MB);
    float* Tbuf  = (float*)(smem + OFF_TB);
    float* stats = (float*)(smem + OFF_ST);

    // stage T^T scaled by 1/8
    for (int i = tid; i < 95 * 64; i += NT) {
        int r = i >> 6, kj = i & 63;
        Tbuf[kj * 97 + r] = Tm[i] * 0.125f;
    }

    for (int p = 0; p < 2; ++p) {
        const float* hsrc = p ? h_vuln : h_perp;
        const uint32_t* w1h = g_w1t_hi[p];
        const uint32_t* w1l = g_w1t_lo[p];
        const uint32_t* w2h = g_w2t_hi[p];
        const uint32_t* w2l = g_w2t_lo[p];
        const float* b1 = p ? bv1 : bp1;
        const float* lg = p ? lgv : lgp;
        const float* lb = p ? lbv : lbp;
        const float* b2 = p ? bv2 : bp2;

        // ===== GEMM1: acc[128,256] = h @ W1, warp tile 32x64 =====
        float acc[2][8][4];
#pragma unroll
        for (int mi = 0; mi < 2; ++mi)
#pragma unroll
            for (int j = 0; j < 8; ++j)
#pragma unroll
                for (int q = 0; q < 4; ++q) acc[mi][j][q] = 0.f;

        for (int kk = 0; kk < 512; kk += 64) {
            __syncthreads();
            // A staging: 128x64 fp32 -> bf16 hi/lo, row stride 144B
#pragma unroll
            for (int z = 0; z < 4; ++z) {
                int i = tid + z * NT;
                int row = i >> 4, gq = i & 15;
                float4 v = *(const float4*)(hsrc + (size_t)(r0 + row) * 512 + kk + gq * 4);
                uint32_t h0, l0, h1, l1;
                split2(v.x, v.y, h0, l0);
                split2(v.z, v.w, h1, l1);
                char* base = smem + OFF_A1 + row * 144 + gq * 8;
                *(uint2*)(base)        = make_uint2(h0, h1);
                *(uint2*)(base + A1LO) = make_uint2(l0, l1);
            }
            // B staging: copy w1t chunk 256x(32 u32), row stride 144B
#pragma unroll
            for (int z = 0; z < 4; ++z) {
                int i = tid + z * NT;
                int row = i >> 3, q = i & 7;
                uint4 vh = *(const uint4*)(w1h + row * 256 + (kk >> 1) + q * 4);
                uint4 vl = *(const uint4*)(w1l + row * 256 + (kk >> 1) + q * 4);
                char* base = smem + OFF_B1 + row * 144 + q * 16;
                *(uint4*)(base)        = vh;
                *(uint4*)(base + B1LO) = vl;
            }
            __syncthreads();

            for (int s = 0; s < 4; ++s) {
                int kb = s * 16;
                uint32_t ah[2][4], al[2][4];
#pragma unroll
                for (int mi = 0; mi < 2; ++mi) {
                    int arow = wm * 32 + mi * 16 + g8 + ((m4 & 1) << 3);
                    int acol = kb + ((m4 & 2) << 2);
                    uint32_t ao = sb + OFF_A1 + arow * 144 + acol * 2;
                    ldsm4(ah[mi], ao);
                    ldsm4(al[mi], ao + A1LO);
                }
#pragma unroll
                for (int jp = 0; jp < 4; ++jp) {
                    int brow = wn * 64 + jp * 16 + g8 + ((m4 & 2) << 2);
                    int bcol = kb + ((m4 & 1) << 3);
                    uint32_t bo = sb + OFF_B1 + brow * 144 + bcol * 2;
                    uint32_t bh[4], bl[4];
                    ldsm4(bh, bo);
                    ldsm4(bl, bo + B1LO);
#pragma unroll
                    for (int mi = 0; mi < 2; ++mi) {
#pragma unroll
                        for (int hh = 0; hh < 2; ++hh) {
                            int j = jp * 2 + hh;
                            mma16816(acc[mi][j], ah[mi], bh[2 * hh], bh[2 * hh + 1]);
                            mma16816(acc[mi][j], ah[mi], bl[2 * hh], bl[2 * hh + 1]);
                            mma16816(acc[mi][j], al[mi], bh[2 * hh], bh[2 * hh + 1]);
                        }
                    }
                }
            }
        }

        // ===== LayerNorm stats =====
        float s1[2][2] = {{0.f, 0.f}, {0.f, 0.f}};
        float s2a[2][2] = {{0.f, 0.f}, {0.f, 0.f}};
#pragma unroll
        for (int j = 0; j < 8; ++j) {
            float2 b1v = *(const float2*)(b1 + wn * 64 + 8 * j + 2 * t);
#pragma unroll
            for (int mi = 0; mi < 2; ++mi) {
                float v0 = acc[mi][j][0] + b1v.x, v1 = acc[mi][j][1] + b1v.y;
                float v2 = acc[mi][j][2] + b1v.x, v3 = acc[mi][j][3] + b1v.y;
                s1[mi][0] += v0 + v1;  s2a[mi][0] += v0 * v0 + v1 * v1;
                s1[mi][1] += v2 + v3;  s2a[mi][1] += v2 * v2 + v3 * v3;
            }
        }
#pragma unroll
        for (int mi = 0; mi < 2; ++mi)
#pragma unroll
            for (int rp = 0; rp < 2; ++rp) {
                s1[mi][rp]  += __shfl_xor_sync(0xFFFFFFFFu, s1[mi][rp], 1);
                s1[mi][rp]  += __shfl_xor_sync(0xFFFFFFFFu, s1[mi][rp], 2);
                s2a[mi][rp] += __shfl_xor_sync(0xFFFFFFFFu, s2a[mi][rp], 1);
                s2a[mi][rp] += __shfl_xor_sync(0xFFFFFFFFu, s2a[mi][rp], 2);
            }
        if (t == 0) {
#pragma unroll
            for (int mi = 0; mi < 2; ++mi)
#pragma unroll
                for (int rp = 0; rp < 2; ++rp) {
                    int row = wm * 32 + mi * 16 + g + 8 * rp;
                    stats[row * 8 + wn * 2]     = s1[mi][rp];
                    stats[row * 8 + wn * 2 + 1] = s2a[mi][rp];
                }
        }
        __syncthreads();
        float mu[2][2], rs[2][2];
#pragma unroll
        for (int mi = 0; mi < 2; ++mi)
#pragma unroll
            for (int rp = 0; rp < 2; ++rp) {
                int row = wm * 32 + mi * 16 + g + 8 * rp;
                float S  = stats[row * 8] + stats[row * 8 + 2] + stats[row * 8 + 4] + stats[row * 8 + 6];
                float S2 = stats[row * 8 + 1] + stats[row * 8 + 3] + stats[row * 8 + 5] + stats[row * 8 + 7];
                float m = S * (1.f / 256.f);
                float var = S2 * (1.f / 256.f) - m * m;
                mu[mi][rp] = m;
                rs[mi][rp] = rsqrtf(var + 1e-5f);
            }

        // ===== GELU + pack -> x slabs (hi/lo, SW128 swizzled 128B rows) =====
        const int xbase = OFF_X + wn * 16384;
#pragma unroll
        for (int j = 0; j < 8; ++j) {
            int cg = wn * 64 + 8 * j + 2 * t;
            float2 b1v = *(const float2*)(b1 + cg);
            float2 lgv = *(const float2*)(lg + cg);
            float2 lbv = *(const float2*)(lb + cg);
#pragma unroll
            for (int mi = 0; mi < 2; ++mi) {
                int rowt = wm * 32 + mi * 16 + g;
                // top row (g)
                {
                    float y0 = (acc[mi][j][0] + b1v.x - mu[mi][0]) * rs[mi][0] * lgv.x + lbv.x;
                    float y1 = (acc[mi][j][1] + b1v.y - mu[mi][0]) * rs[mi][0] * lgv.y + lbv.y;
                    float g0 = 0.5f * y0 * (1.f + erff(y0 * 0.70710678118654752f));
                    float g1 = 0.5f * y1 * (1.f + erff(y1 * 0.70710678118654752f));
                    uint32_t hh, ll;
                    split2(g0, g1, hh, ll);
                    uint32_t off = (uint32_t)(rowt * 128 + (8 * j + 2 * t) * 2);
                    *(uint32_t*)(smem + xbase + SW(off))       = hh;
                    *(uint32_t*)(smem + xbase + XLO + SW(off)) = ll;
                }
                // bottom row (g+8)
                {
                    float y0 = (acc[mi][j][2] + b1v.x - mu[mi][1]) * rs[mi][1] * lgv.x + lbv.x;
                    float y1 = (acc[mi][j][3] + b1v.y - mu[mi][1]) * rs[mi][1] * lgv.y + lbv.y;
                    float g0 = 0.5f * y0 * (1.f + erff(y0 * 0.70710678118654752f));
                    float g1 = 0.5f * y1 * (1.f + erff(y1 * 0.70710678118654752f));
                    uint32_t hh, ll;
                    split2(g0, g1, hh, ll);
                    uint32_t off = (uint32_t)((rowt + 8) * 128 + (8 * j + 2 * t) * 2);
                    *(uint32_t*)(smem + xbase + SW(off))       = hh;
                    *(uint32_t*)(smem + xbase + XLO + SW(off)) = ll;
                }
            }
        }
        // init mbuf[p] with bias b2
        for (int i = tid; i < 8192; i += NT) {
            int row = i >> 6, c = i & 63;
            mbuf[p * 8320 + row * 65 + c] = b2[c];
        }
        __syncthreads();

        // ===== GEMM2: split-K, warp computes 32x64 partial over k = wn*64..+64 =====
        float a2[2][8][4];
#pragma unroll
        for (int mi = 0; mi < 2; ++mi)
#pragma unroll
            for (int j = 0; j < 8; ++j)
#pragma unroll
                for (int q = 0; q < 4; ++q) a2[mi][j][q] = 0.f;

#pragma unroll
        for (int s = 0; s < 4; ++s) {
            uint32_t ah[2][4], al[2][4];
#pragma unroll
            for (int mi = 0; mi < 2; ++mi) {
                int arow = wm * 32 + mi * 16 + g8 + ((m4 & 1) << 3);
                int lcol = s * 16 + ((m4 & 2) << 2);
                uint32_t off = SW((uint32_t)(arow * 128 + lcol * 2));
                ldsm4(ah[mi], sb + xbase + off);
                ldsm4(al[mi], sb + xbase + XLO + off);
            }
            int kp0 = wn * 32 + 8 * s + t;
#pragma unroll
            for (int j2 = 0; j2 < 8; ++j2) {
                int nrow = 8 * j2 + g;
                uint32_t b0h = w2h[nrow * 128 + kp0], b1h = w2h[nrow * 128 + kp0 + 4];
                uint32_t b0l = w2l[nrow * 128 + kp0], b1l = w2l[nrow * 128 + kp0 + 4];
#pragma unroll
                for (int mi = 0; mi < 2; ++mi) {
                    mma16816(a2[mi][j2], ah[mi], b0h, b1h);
                    mma16816(a2[mi][j2], ah[mi], b0l, b1l);
                    mma16816(a2[mi][j2], al[mi], b0h, b1h);
                }
            }
        }
        // combine partials
        float* mb = mbuf + p * 8320;
#pragma unroll
        for (int mi = 0; mi < 2; ++mi) {
            int rowt = wm * 32 + mi * 16 + g;
#pragma unroll
            for (int j2 = 0; j2 < 8; ++j2) {
                int c0 = 8 * j2 + 2 * t;
                atomicAdd(&mb[rowt * 65 + c0],       a2[mi][j2][0]);
                atomicAdd(&mb[rowt * 65 + c0 + 1],   a2[mi][j2][1]);
                atomicAdd(&mb[(rowt + 8) * 65 + c0],     a2[mi][j2][2]);
                atomicAdd(&mb[(rowt + 8) * 65 + c0 + 1], a2[mi][j2][3]);
            }
        }
        __syncthreads();
    }

    // ===== Cayley contraction with gw -> P[128,64] =====
    float gwr[8];
#pragma unroll
    for (int n = 0; n < 8; ++n) gwr[n] = gw[n];
    const int MASKc[8] = {0, 1, 2, 4, 3, 5, 6, 7};
    float* pbuf = (float*)(smem + OFF_X);   // [128][65]
    {
        int row = tid & 127;
        int kb2 = (tid >> 7) * 2;
        const float* mp = mbuf + row * 65;
        const float* mv = mbuf + 8320 + row * 65;
#pragma unroll
        for (int kk2 = 0; kk2 < 2; ++kk2) {
            int k = kb2 + kk2;
            float mpv[8], mvv[8];
#pragma unroll
            for (int i = 0; i < 8; ++i) { mpv[i] = mp[k * 8 + i]; mvv[i] = mv[k * 8 + i]; }
            float Q[8];
#pragma unroll
            for (int m = 0; m < 8; ++m) {
                float q = 0.f;
#pragma unroll
                for (int j = 0; j < 8; ++j) {
                    int am = MASKc[m], bm = MASKc[j];
                    int sw = __popc((am >> 1) & bm) + __popc((am >> 2) & bm);
                    float sg = (sw & 1) ? -1.f : 1.f;
                    q += sg * gwr[MASKc[am ^ bm]] * mvv[j];
                }
                Q[m] = q;
            }
#pragma unroll
            for (int j = 0; j < 8; ++j) {
                float pv = 0.f;
#pragma unroll
                for (int i = 0; i < 8; ++i) {
                    int am = MASKc[i], bm = MASKc[j];
                    int sw = __popc((am >> 1) & bm) + __popc((am >> 2) & bm);
                    float sg = (sw & 1) ? -1.f : 1.f;
                    pv += sg * mpv[i] * Q[MASKc[am ^ bm]];
                }
                pbuf[row * 65 + k * 8 + j] = pv;
            }
        }
    }
    __syncthreads();

    // ===== out[128,95] = P[128,64] @ Tbuf[64,95] =====
    {
        const int ty = tid >> 4;   // 0..31, 4 rows each
        const int tx = tid & 15;   // cols tx + 16j, j<6
        float acc3[4][6];
#pragma unroll
        for (int i = 0; i < 4; ++i)
#pragma unroll
            for (int j = 0; j < 6; ++j) acc3[i][j] = 0.f;
#pragma unroll 8
        for (int k = 0; k < 64; ++k) {
            float a[4], b[6];
#pragma unroll
            for (int i = 0; i < 4; ++i) a[i] = pbuf[(ty * 4 + i) * 65 + k];
#pragma unroll
            for (int j = 0; j < 6; ++j) {
                int col = tx + 16 * j;
                b[j] = (col < 95) ? Tbuf[k * 97 + col] : 0.f;
            }
#pragma unroll
            for (int i = 0; i < 4; ++i)
#pragma unroll
                for (int j = 0; j < 6; ++j) acc3[i][j] += a[i] * b[j];
        }
#pragma unroll
        for (int i = 0; i < 4; ++i)
#pragma unroll
            for (int j = 0; j < 6; ++j) {
                int col = tx + 16 * j;
                if (col < 95)
                    out[(size_t)(r0 + ty * 4 + i) * 95 + col] = acc3[i][j];
            }
    }
}

extern "C" void kernel_launch(void* const* d_in, const int* in_sizes, int n_in,
                              void* d_out, int out_size) {
    const float* h_perp = (const float*)d_in[0];
    const float* h_vuln = (const float*)d_in[1];
    const float* Wp1 = (const float*)d_in[2];
    const float* bp1 = (const float*)d_in[3];
    const float* lgp = (const float*)d_in[4];
    const float* lbp = (const float*)d_in[5];
    const float* Wp2 = (const float*)d_in[6];
    const float* bp2 = (const float*)d_in[7];
    const float* Wv1 = (const float*)d_in[8];
    const float* bv1 = (const float*)d_in[9];
    const float* lgv = (const float*)d_in[10];
    const float* lbv = (const float*)d_in[11];
    const float* Wv2 = (const float*)d_in[12];
    const float* bv2 = (const float*)d_in[13];
    const float* Tm  = (const float*)d_in[14];
    const float* gw  = (const float*)d_in[15];
    float* out = (float*)d_out;

    int B = in_sizes[0] / 512;   // 16384
    int grid = B / TB;           // 128

    prep_kernel<<<(65536 + 8192 + 255) / 256, 256>>>(Wp1, Wv1, Wp2, Wv2);

    cudaFuncSetAttribute(clifford_mma_kernel,
                         cudaFuncAttributeMaxDynamicSharedMemorySize, SMEM_BYTES);
    clifford_mma_kernel<<<grid, NT, SMEM_BYTES>>>(
        h_perp, h_vuln, bp1, lgp, lbp, bp2, bv1, lgv, lbv, bv2, Tm, gw, out);
}